// round 1
// baseline (speedup 1.0000x reference)
#include <cuda_runtime.h>
#include <cstdint>

#define NN 50000
#define EE 800000
#define DD 128
#define LL 3

// ---------------- device scratch (no allocs allowed) ----------------
__device__ float g_buf0[NN * DD];   // layer-0 output
__device__ float g_buf1[NN * DD];   // layer-1 output
__device__ float g_agg [NN * DD];   // per-layer aggregation result
__device__ int   g_rowptr[NN + 1];
__device__ int   g_counts[NN];
__device__ int   g_srcs  [EE];      // CSR payload: src node per (dst-sorted) slot
__device__ int   g_src_in[EE];      // converted int32 src
__device__ int   g_dst_in[EE];      // converted int32 dst
__device__ int   g_is32;

// ---------------- CSR build ----------------
__global__ void zero_counts_kernel(int also_flag) {
    int i = blockIdx.x * blockDim.x + threadIdx.x;
    if (i < NN) g_counts[i] = 0;
    if (also_flag && i == 0) g_is32 = 0;
}

// If edge_index is int64, every odd 32-bit word (high half of a value in
// [0, 50000)) is zero. If int32, odd words are real indices (not all zero).
__global__ void detect_kernel(const unsigned int* __restrict__ w) {
    int i = blockIdx.x * blockDim.x + threadIdx.x;
    if (i < EE) {
        if (w[2 * i + 1] != 0u) g_is32 = 1;  // benign race, idempotent
    }
}

__global__ void convert_kernel(const void* __restrict__ edges) {
    int e = blockIdx.x * blockDim.x + threadIdx.x;
    if (e >= EE) return;
    if (g_is32) {
        const int* p = (const int*)edges;
        g_src_in[e] = p[e];
        g_dst_in[e] = p[EE + e];
    } else {
        const long long* p = (const long long*)edges;
        g_src_in[e] = (int)p[e];
        g_dst_in[e] = (int)p[EE + e];
    }
}

__global__ void hist_kernel() {
    int e = blockIdx.x * blockDim.x + threadIdx.x;
    if (e < EE) atomicAdd(&g_counts[g_dst_in[e]], 1);
}

// Single-block exclusive scan of g_counts -> g_rowptr (50001 entries).
__global__ void scan_kernel() {
    __shared__ int sums[1024];
    int tid = threadIdx.x;
    const int CH = (NN + 1023) / 1024;  // 49
    int beg = tid * CH;
    int end = beg + CH; if (end > NN) end = NN;
    int s = 0;
    for (int i = beg; i < end; i++) s += g_counts[i];
    sums[tid] = s;
    __syncthreads();
    #pragma unroll
    for (int off = 1; off < 1024; off <<= 1) {
        int v = (tid >= off) ? sums[tid - off] : 0;
        __syncthreads();
        sums[tid] += v;
        __syncthreads();
    }
    int run = tid ? sums[tid - 1] : 0;
    for (int i = beg; i < end; i++) { g_rowptr[i] = run; run += g_counts[i]; }
    if (tid == 1023) g_rowptr[NN] = sums[1023];
}

__global__ void fill_kernel() {
    int e = blockIdx.x * blockDim.x + threadIdx.x;
    if (e >= EE) return;
    int d = g_dst_in[e];
    int pos = g_rowptr[d] + atomicAdd(&g_counts[d], 1);
    g_srcs[pos] = g_src_in[e];
}

// ---------------- aggregation: one warp per destination node ----------------
__global__ void agg_kernel(const float* __restrict__ x) {
    int gw   = (blockIdx.x * blockDim.x + threadIdx.x) >> 5;
    int lane = threadIdx.x & 31;
    if (gw >= NN) return;
    int beg = g_rowptr[gw], end = g_rowptr[gw + 1];
    float4 acc = make_float4(0.f, 0.f, 0.f, 0.f);
    const float* xb = x + lane * 4;
    for (int e = beg; e < end; e++) {
        int s = g_srcs[e];
        float4 v = *(const float4*)(xb + (size_t)s * DD);
        acc.x += v.x; acc.y += v.y; acc.z += v.z; acc.w += v.w;
    }
    *(float4*)(g_agg + (size_t)gw * DD + lane * 4) = acc;
}

// ---------------- fused GEMM: out = agg @ Wrel + x @ Wroot + b ----------------
// Virtual A = [agg | x]  (N x 256), virtual B = [Wrel ; Wroot] (256 x 128).
// BM=64, BN=128, BK=16, 256 threads, each thread computes 8x4 outputs.
__global__ void __launch_bounds__(256) gemm_kernel(
    const float* __restrict__ xin,
    const float* __restrict__ Wrel, const float* __restrict__ Wroot,
    const float* __restrict__ bias,
    float* __restrict__ out)
{
    __shared__ float As[16][64];
    __shared__ float Bs[16][128];

    int tid  = threadIdx.x;
    int row0 = blockIdx.x * 64;
    int tx   = tid & 31;      // 32 threads over N
    int ty   = tid >> 5;      // 8 threads over M
    int m0   = ty * 8;
    int c0   = tx * 4;

    float acc[8][4];
    #pragma unroll
    for (int i = 0; i < 8; i++)
        #pragma unroll
        for (int j = 0; j < 4; j++) acc[i][j] = 0.f;

    // A-load indices (one float4 per thread per tile)
    int am = tid >> 2;        // 0..63
    int akq = tid & 3;        // 0..3  (float4 within the 16-wide k slice)

    #pragma unroll 1
    for (int kt = 0; kt < 16; kt++) {            // 256 / 16
        int half = kt >> 3;                      // 0: (agg,Wrel)  1: (x,Wroot)
        int kl0  = (kt & 7) * 16;                // k offset within 0..127

        const float* Aptr = half ? xin   : g_agg;
        const float* Bptr = half ? Wroot : Wrel;

        // load A tile (transposed into As[k][m])
        {
            int row = row0 + am;
            float4 v = make_float4(0.f, 0.f, 0.f, 0.f);
            if (row < NN)
                v = *(const float4*)(Aptr + (size_t)row * DD + kl0 + akq * 4);
            As[akq * 4 + 0][am] = v.x;
            As[akq * 4 + 1][am] = v.y;
            As[akq * 4 + 2][am] = v.z;
            As[akq * 4 + 3][am] = v.w;
        }
        // load B tile (straight linear copy, rows are contiguous)
        {
            const float4* W4 = (const float4*)(Bptr + (size_t)kl0 * DD);
            ((float4*)Bs)[tid]       = W4[tid];
            ((float4*)Bs)[tid + 256] = W4[tid + 256];
        }
        __syncthreads();

        #pragma unroll
        for (int k = 0; k < 16; k++) {
            float a[8], b[4];
            #pragma unroll
            for (int i = 0; i < 8; i++) a[i] = As[k][m0 + i];
            #pragma unroll
            for (int j = 0; j < 4; j++) b[j] = Bs[k][c0 + j];
            #pragma unroll
            for (int i = 0; i < 8; i++)
                #pragma unroll
                for (int j = 0; j < 4; j++)
                    acc[i][j] += a[i] * b[j];
        }
        __syncthreads();
    }

    float b0 = bias[c0 + 0], b1 = bias[c0 + 1], b2 = bias[c0 + 2], b3 = bias[c0 + 3];
    #pragma unroll
    for (int i = 0; i < 8; i++) {
        int row = row0 + m0 + i;
        if (row < NN) {
            float4 o;
            o.x = acc[i][0] + b0;
            o.y = acc[i][1] + b1;
            o.z = acc[i][2] + b2;
            o.w = acc[i][3] + b3;
            *(float4*)(out + (size_t)row * DD + c0) = o;
        }
    }
}

// ---------------- launch ----------------
extern "C" void kernel_launch(void* const* d_in, const int* in_sizes, int n_in,
                              void* d_out, int out_size) {
    const float* x     = (const float*)d_in[0];
    const void*  edges = d_in[1];
    const float* Wrel  = (const float*)d_in[2];
    const float* Wroot = (const float*)d_in[3];
    const float* bias  = (const float*)d_in[4];
    float*       out   = (float*)d_out;

    float *buf0, *buf1;
    cudaGetSymbolAddress((void**)&buf0, g_buf0);
    cudaGetSymbolAddress((void**)&buf1, g_buf1);

    const int T = 256;
    int gbN = (NN + T - 1) / T;
    int gbE = (EE + T - 1) / T;

    // CSR build (dst-keyed)
    zero_counts_kernel<<<gbN, T>>>(1);
    detect_kernel<<<gbE, T>>>((const unsigned int*)edges);
    convert_kernel<<<gbE, T>>>(edges);
    hist_kernel<<<gbE, T>>>();
    scan_kernel<<<1, 1024>>>();
    zero_counts_kernel<<<gbN, T>>>(0);
    fill_kernel<<<gbE, T>>>();

    int aggBlocks  = (NN * 32 + T - 1) / T;   // one warp per node
    int gemmBlocks = (NN + 63) / 64;

    const float* cur = x;
    float* outs[LL] = { buf0, buf1, out };
    for (int l = 0; l < LL; l++) {
        agg_kernel<<<aggBlocks, T>>>(cur);
        gemm_kernel<<<gemmBlocks, T>>>(cur,
                                       Wrel  + (size_t)l * DD * DD,
                                       Wroot + (size_t)l * DD * DD,
                                       bias  + (size_t)l * DD,
                                       outs[l]);
        cur = outs[l];
    }
}

// round 3
// speedup vs baseline: 1.3722x; 1.3722x over previous
#include <cuda_runtime.h>
#include <cuda_bf16.h>
#include <cstdint>

#define NN 50000
#define EE 800000
#define DD 128
#define LL 3

// ---------------- device scratch ----------------
__device__ float g_buf0[NN * DD];
__device__ float g_buf1[NN * DD];
__device__ float g_agg [NN * DD];
__device__ int   g_rowptr[NN + 1];
__device__ int   g_counts[NN];
__device__ int   g_srcs  [EE];
__device__ int   g_src_in[EE];
__device__ int   g_dst_in[EE];
__device__ int   g_is32;
// transposed bf16 weights: [layer][n=128][k=256] (k<128 -> Wrel, else Wroot)
__device__ unsigned short g_Bth[LL * DD * 2 * DD];
__device__ unsigned short g_Btl[LL * DD * 2 * DD];

// ---------------- CSR build ----------------
__global__ void zero_counts_kernel(int also_flag) {
    int i = blockIdx.x * blockDim.x + threadIdx.x;
    if (i < NN) g_counts[i] = 0;
    if (also_flag && i == 0) g_is32 = 0;
}

__global__ void detect_kernel(const unsigned int* __restrict__ w) {
    int i = blockIdx.x * blockDim.x + threadIdx.x;
    if (i < EE) { if (w[2 * i + 1] != 0u) g_is32 = 1; }
}

__global__ void convert_hist_kernel(const void* __restrict__ edges) {
    int e = blockIdx.x * blockDim.x + threadIdx.x;
    if (e >= EE) return;
    int s, d;
    if (g_is32) {
        const int* p = (const int*)edges;
        s = p[e]; d = p[EE + e];
    } else {
        const long long* p = (const long long*)edges;
        s = (int)p[e]; d = (int)p[EE + e];
    }
    g_src_in[e] = s;
    g_dst_in[e] = d;
    atomicAdd(&g_counts[d], 1);
}

__global__ void scan_kernel() {
    __shared__ int sums[1024];
    int tid = threadIdx.x;
    const int CH = (NN + 1023) / 1024;
    int beg = tid * CH;
    int end = beg + CH; if (end > NN) end = NN;
    int s = 0;
    for (int i = beg; i < end; i++) s += g_counts[i];
    sums[tid] = s;
    __syncthreads();
    #pragma unroll
    for (int off = 1; off < 1024; off <<= 1) {
        int v = (tid >= off) ? sums[tid - off] : 0;
        __syncthreads();
        sums[tid] += v;
        __syncthreads();
    }
    int run = tid ? sums[tid - 1] : 0;
    for (int i = beg; i < end; i++) { g_rowptr[i] = run; run += g_counts[i]; }
    if (tid == 1023) g_rowptr[NN] = sums[1023];
}

__global__ void fill_kernel() {
    int e = blockIdx.x * blockDim.x + threadIdx.x;
    if (e >= EE) return;
    int d = g_dst_in[e];
    int pos = g_rowptr[d] + atomicAdd(&g_counts[d], 1);
    g_srcs[pos] = g_src_in[e];
}

// ---------------- weight prep: transpose + split to bf16 hi/lo ----------------
__global__ void wprep_kernel(const float* __restrict__ Wrel,
                             const float* __restrict__ Wroot) {
    int idx = blockIdx.x * blockDim.x + threadIdx.x;   // LL * 256 * 128
    if (idx >= LL * 256 * DD) return;
    int l = idx / (256 * DD);
    int r = idx - l * 256 * DD;
    int k = r / DD;
    int n = r - k * DD;
    float w = (k < DD) ? Wrel[(size_t)l * DD * DD + k * DD + n]
                       : Wroot[(size_t)l * DD * DD + (k - DD) * DD + n];
    __nv_bfloat16 hi = __float2bfloat16(w);
    float lo = w - __bfloat162float(hi);
    __nv_bfloat16 lob = __float2bfloat16(lo);
    size_t o = (size_t)l * DD * 256 + (size_t)n * 256 + k;
    g_Bth[o] = *(unsigned short*)&hi;
    g_Btl[o] = *(unsigned short*)&lob;
}

// ---------------- aggregation: one warp per destination node ----------------
__global__ void agg_kernel(const float* __restrict__ x) {
    int gw   = (blockIdx.x * blockDim.x + threadIdx.x) >> 5;
    int lane = threadIdx.x & 31;
    if (gw >= NN) return;
    int beg = g_rowptr[gw], end = g_rowptr[gw + 1];
    float4 acc = make_float4(0.f, 0.f, 0.f, 0.f);
    const float* xb = x + lane * 4;
    for (int e = beg; e < end; e++) {
        int s = g_srcs[e];
        float4 v = *(const float4*)(xb + (size_t)s * DD);
        acc.x += v.x; acc.y += v.y; acc.z += v.z; acc.w += v.w;
    }
    *(float4*)(g_agg + (size_t)gw * DD + lane * 4) = acc;
}

// ---------------- tensor-core GEMM via mma.sync (HMMA, works on sm_103) ------
// out[m][n] = sum_k A[m][k] W[k][n] + bias[n];  A = [agg | x]  (virtual K=256).
// Split bf16: acc += Ahi*Bhi + Ahi*Blo + Alo*Bhi.
// BM=128, BN=128, BK=32, 256 threads = 8 warps, warp tile 64x32.
// smem rows padded to 40 bf16 (80B) -> conflict-free fragment loads.

#define BK 32
#define ROWE 40                       // padded row length (elements)
#define ROWB 80                       // padded row length (bytes)
#define BUFB 40960                    // 4 planes * 128 rows * 80B
#define OFF_AH 0
#define OFF_AL 10240
#define OFF_BH 20480
#define OFF_BL 30720

__device__ __forceinline__ void mma16816(float* c, const uint32_t* a, const uint32_t* b) {
    asm volatile(
        "mma.sync.aligned.m16n8k16.row.col.f32.bf16.bf16.f32 "
        "{%0,%1,%2,%3}, {%4,%5,%6,%7}, {%8,%9}, {%0,%1,%2,%3};"
        : "+f"(c[0]), "+f"(c[1]), "+f"(c[2]), "+f"(c[3])
        : "r"(a[0]), "r"(a[1]), "r"(a[2]), "r"(a[3]), "r"(b[0]), "r"(b[1]));
}

__device__ __forceinline__ uint32_t pack_bf2f(float a, float b) {
    __nv_bfloat16 ha = __float2bfloat16(a), hb = __float2bfloat16(b);
    uint16_t ua = *(uint16_t*)&ha, ub = *(uint16_t*)&hb;
    return (uint32_t)ua | ((uint32_t)ub << 16);
}

__global__ void __launch_bounds__(256) gemm_mma_kernel(
    const float* __restrict__ xin,
    int layer,
    const float* __restrict__ bias,
    float* __restrict__ out)
{
    extern __shared__ char smem[];
    int tid  = threadIdx.x;
    int wid  = tid >> 5;
    int lane = tid & 31;
    int g    = lane >> 2;             // fragment group row
    int t    = lane & 3;              // fragment group col
    int row0 = blockIdx.x * 128;
    int m0w  = (wid >> 2) * 64;
    int n0w  = (wid & 3) * 32;

    const uint32_t* Bth = (const uint32_t*)(g_Bth + (size_t)layer * DD * 256);
    const uint32_t* Btl = (const uint32_t*)(g_Btl + (size_t)layer * DD * 256);

    float acc[4][4][4];
    #pragma unroll
    for (int i = 0; i < 4; i++)
        #pragma unroll
        for (int j = 0; j < 4; j++)
            #pragma unroll
            for (int q = 0; q < 4; q++) acc[i][j][q] = 0.f;

    float4   av[4];
    uint32_t bhv[8], blv[8];

    // staging-load for chunk c (global -> regs)
    auto load_regs = [&](int c) {
        int kv0 = c * BK;
        const float* src = (kv0 < DD) ? g_agg : xin;
        int kc = kv0 & 127;
        #pragma unroll
        for (int j = 0; j < 4; j++) {
            int p = j * 256 + tid;        // 0..1023
            int m = p >> 3;
            int kq = p & 7;
            int grow = row0 + m;
            av[j] = make_float4(0.f, 0.f, 0.f, 0.f);
            if (grow < NN)
                av[j] = *(const float4*)(src + (size_t)grow * DD + kc + 4 * kq);
        }
        #pragma unroll
        for (int j = 0; j < 8; j++) {
            int p = j * 256 + tid;        // 0..2047
            int n = p >> 4;
            int kp = p & 15;
            int ui = n * 128 + c * 16 + kp;   // uint index into [n][256bf16]
            bhv[j] = Bth[ui];
            blv[j] = Btl[ui];
        }
    };

    // convert + store regs -> smem buffer
    auto store_smem = [&](int buf) {
        char* base = smem + buf * BUFB;
        #pragma unroll
        for (int j = 0; j < 4; j++) {
            int p = j * 256 + tid;
            int m = p >> 3;
            int kq = p & 7;
            float4 v = av[j];
            float lx = v.x - __bfloat162float(__float2bfloat16(v.x));
            float ly = v.y - __bfloat162float(__float2bfloat16(v.y));
            float lz = v.z - __bfloat162float(__float2bfloat16(v.z));
            float lw = v.w - __bfloat162float(__float2bfloat16(v.w));
            uint32_t off = (uint32_t)m * ROWB + 8 * kq;
            *(uint32_t*)(base + OFF_AH + off)     = pack_bf2f(v.x, v.y);
            *(uint32_t*)(base + OFF_AH + off + 4) = pack_bf2f(v.z, v.w);
            *(uint32_t*)(base + OFF_AL + off)     = pack_bf2f(lx, ly);
            *(uint32_t*)(base + OFF_AL + off + 4) = pack_bf2f(lz, lw);
        }
        #pragma unroll
        for (int j = 0; j < 8; j++) {
            int p = j * 256 + tid;
            int n = p >> 4;
            int kp = p & 15;
            uint32_t off = (uint32_t)n * ROWB + 4 * kp;
            *(uint32_t*)(base + OFF_BH + off) = bhv[j];
            *(uint32_t*)(base + OFF_BL + off) = blv[j];
        }
    };

    load_regs(0);
    store_smem(0);
    __syncthreads();

    #pragma unroll 1
    for (int c = 0; c < 8; c++) {
        if (c < 7) load_regs(c + 1);

        const char* base = smem + (c & 1) * BUFB;
        #pragma unroll
        for (int s = 0; s < 2; s++) {
            uint32_t ah[4][4], al[4][4], bh[4][2], bl[4][2];
            #pragma unroll
            for (int mt = 0; mt < 4; mt++) {
                uint32_t r0 = (uint32_t)(m0w + mt * 16 + g) * ROWB + s * 32 + 4 * t;
                uint32_t r1 = r0 + 8 * ROWB;
                ah[mt][0] = *(const uint32_t*)(base + OFF_AH + r0);
                ah[mt][1] = *(const uint32_t*)(base + OFF_AH + r1);
                ah[mt][2] = *(const uint32_t*)(base + OFF_AH + r0 + 16);
                ah[mt][3] = *(const uint32_t*)(base + OFF_AH + r1 + 16);
                al[mt][0] = *(const uint32_t*)(base + OFF_AL + r0);
                al[mt][1] = *(const uint32_t*)(base + OFF_AL + r1);
                al[mt][2] = *(const uint32_t*)(base + OFF_AL + r0 + 16);
                al[mt][3] = *(const uint32_t*)(base + OFF_AL + r1 + 16);
            }
            #pragma unroll
            for (int nt = 0; nt < 4; nt++) {
                uint32_t rb = (uint32_t)(n0w + nt * 8 + g) * ROWB + s * 32 + 4 * t;
                bh[nt][0] = *(const uint32_t*)(base + OFF_BH + rb);
                bh[nt][1] = *(const uint32_t*)(base + OFF_BH + rb + 16);
                bl[nt][0] = *(const uint32_t*)(base + OFF_BL + rb);
                bl[nt][1] = *(const uint32_t*)(base + OFF_BL + rb + 16);
            }
            #pragma unroll
            for (int mt = 0; mt < 4; mt++)
                #pragma unroll
                for (int nt = 0; nt < 4; nt++) {
                    mma16816(acc[mt][nt], ah[mt], bh[nt]);
                    mma16816(acc[mt][nt], ah[mt], bl[nt]);
                    mma16816(acc[mt][nt], al[mt], bh[nt]);
                }
        }
        __syncthreads();
        if (c < 7) store_smem((c + 1) & 1);
        __syncthreads();
    }

    // epilogue: bias + store (c0,c1)=(g,2t..2t+1), (c2,c3)=(g+8,2t..)
    #pragma unroll
    for (int nt = 0; nt < 4; nt++) {
        int col = n0w + nt * 8 + 2 * t;
        float b0 = bias[col], b1 = bias[col + 1];
        #pragma unroll
        for (int mt = 0; mt < 4; mt++) {
            int r = row0 + m0w + mt * 16 + g;
            if (r < NN) {
                float2 o0 = make_float2(acc[mt][nt][0] + b0, acc[mt][nt][1] + b1);
                *(float2*)(out + (size_t)r * DD + col) = o0;
            }
            if (r + 8 < NN) {
                float2 o1 = make_float2(acc[mt][nt][2] + b0, acc[mt][nt][3] + b1);
                *(float2*)(out + (size_t)(r + 8) * DD + col) = o1;
            }
        }
    }
}

// ---------------- launch ----------------
extern "C" void kernel_launch(void* const* d_in, const int* in_sizes, int n_in,
                              void* d_out, int out_size) {
    const float* x     = (const float*)d_in[0];
    const void*  edges = d_in[1];
    const float* Wrel  = (const float*)d_in[2];
    const float* Wroot = (const float*)d_in[3];
    const float* bias  = (const float*)d_in[4];
    float*       out   = (float*)d_out;

    float *buf0, *buf1;
    cudaGetSymbolAddress((void**)&buf0, g_buf0);
    cudaGetSymbolAddress((void**)&buf1, g_buf1);

    cudaFuncSetAttribute(gemm_mma_kernel,
                         cudaFuncAttributeMaxDynamicSharedMemorySize, 2 * BUFB);

    const int T = 256;
    int gbN = (NN + T - 1) / T;
    int gbE = (EE + T - 1) / T;

    zero_counts_kernel<<<gbN, T>>>(1);
    detect_kernel<<<gbE, T>>>((const unsigned int*)edges);
    convert_hist_kernel<<<gbE, T>>>(edges);
    scan_kernel<<<1, 1024>>>();
    zero_counts_kernel<<<gbN, T>>>(0);
    fill_kernel<<<gbE, T>>>();
    wprep_kernel<<<(LL * 256 * DD + T - 1) / T, T>>>(Wrel, Wroot);

    int aggBlocks  = (NN * 32 + T - 1) / T;
    int gemmBlocks = (NN + 127) / 128;   // 391

    const float* cur = x;
    float* outs[LL] = { buf0, buf1, out };
    for (int l = 0; l < LL; l++) {
        agg_kernel<<<aggBlocks, T>>>(cur);
        gemm_mma_kernel<<<gemmBlocks, T, 2 * BUFB>>>(cur, l, bias + (size_t)l * DD,
                                                     outs[l]);
        cur = outs[l];
    }
}

// round 4
// speedup vs baseline: 1.7006x; 1.2393x over previous
#include <cuda_runtime.h>
#include <cuda_bf16.h>
#include <cstdint>

#define NN 50000
#define EE 800000
#define DD 128
#define LL 3
#define NB 196                        // scan blocks: ceil(50000/256)

// ---------------- device scratch ----------------
__device__ float g_buf0[NN * DD];
__device__ float g_buf1[NN * DD];
__device__ float g_agg [NN * DD];
__device__ int   g_rowptr[NN + 1];
__device__ int   g_counts[NN];
__device__ int   g_bsum[NB];
__device__ int   g_srcs  [EE];
__device__ int   g_src_in[EE];
__device__ int   g_dst_in[EE];
__device__ int   g_is32;
// transposed bf16 weights: [layer][n=128][k=256] (k<128 -> Wrel, else Wroot)
__device__ unsigned short g_Bth[LL * DD * 2 * DD];
__device__ unsigned short g_Btl[LL * DD * 2 * DD];

// ---------------- CSR build ----------------
__global__ void zero_counts_kernel() {
    int i = blockIdx.x * blockDim.x + threadIdx.x;
    if (i < NN) g_counts[i] = 0;
    if (i == 0) g_is32 = 0;
}

// Sample first 16384 odd 32-bit words. int64 edges -> all high halves zero.
// int32 edges -> these are uniform indices in [0,50000); all-zero impossible.
__global__ void detect_kernel(const unsigned int* __restrict__ w) {
    int i = blockIdx.x * blockDim.x + threadIdx.x;   // 0..4095
    unsigned int acc = 0;
    #pragma unroll
    for (int j = 0; j < 4; j++) acc |= w[2 * (i * 4 + j) + 1];
    if (acc) g_is32 = 1;
}

__global__ void convert_hist_kernel(const void* __restrict__ edges) {
    int e = blockIdx.x * blockDim.x + threadIdx.x;
    if (e >= EE) return;
    int s, d;
    if (g_is32) {
        const int* p = (const int*)edges;
        s = p[e]; d = p[EE + e];
    } else {
        const long long* p = (const long long*)edges;
        s = (int)p[e]; d = (int)p[EE + e];
    }
    g_src_in[e] = s;
    g_dst_in[e] = d;
    atomicAdd(&g_counts[d], 1);
}

// ---- 3-phase scan: per-block reduce -> scan block sums -> local scan+offset
__global__ void scan_red_kernel() {
    __shared__ int s[256];
    int b = blockIdx.x, t = threadIdx.x;
    int i = b * 256 + t;
    s[t] = (i < NN) ? g_counts[i] : 0;
    __syncthreads();
    #pragma unroll
    for (int o = 128; o > 0; o >>= 1) {
        if (t < o) s[t] += s[t + o];
        __syncthreads();
    }
    if (t == 0) g_bsum[b] = s[0];
}

__global__ void scan_mid_kernel() {
    __shared__ int s[256];
    int t = threadIdx.x;
    int v = (t < NB) ? g_bsum[t] : 0;
    s[t] = v;
    __syncthreads();
    #pragma unroll
    for (int o = 1; o < 256; o <<= 1) {
        int u = (t >= o) ? s[t - o] : 0;
        __syncthreads();
        s[t] += u;
        __syncthreads();
    }
    if (t < NB) g_bsum[t] = s[t] - v;          // exclusive block offsets
    if (t == 255) g_rowptr[NN] = s[255];       // total
}

__global__ void scan_final_kernel() {
    __shared__ int s[256];
    int b = blockIdx.x, t = threadIdx.x;
    int i = b * 256 + t;
    int v = (i < NN) ? g_counts[i] : 0;
    s[t] = v;
    __syncthreads();
    #pragma unroll
    for (int o = 1; o < 256; o <<= 1) {
        int u = (t >= o) ? s[t - o] : 0;
        __syncthreads();
        s[t] += u;
        __syncthreads();
    }
    if (i < NN) {
        g_rowptr[i] = g_bsum[b] + s[t] - v;    // exclusive scan
        g_counts[i] = 0;                       // reset cursor for fill
    }
}

__global__ void fill_kernel() {
    int e = blockIdx.x * blockDim.x + threadIdx.x;
    if (e >= EE) return;
    int d = g_dst_in[e];
    int pos = g_rowptr[d] + atomicAdd(&g_counts[d], 1);
    g_srcs[pos] = g_src_in[e];
}

// ---------------- weight prep: transpose + split to bf16 hi/lo ----------------
__global__ void wprep_kernel(const float* __restrict__ Wrel,
                             const float* __restrict__ Wroot) {
    int idx = blockIdx.x * blockDim.x + threadIdx.x;   // LL * 256 * 128
    if (idx >= LL * 256 * DD) return;
    int l = idx / (256 * DD);
    int r = idx - l * 256 * DD;
    int k = r / DD;
    int n = r - k * DD;
    float w = (k < DD) ? Wrel[(size_t)l * DD * DD + k * DD + n]
                       : Wroot[(size_t)l * DD * DD + (k - DD) * DD + n];
    __nv_bfloat16 hi = __float2bfloat16(w);
    float lo = w - __bfloat162float(hi);
    __nv_bfloat16 lob = __float2bfloat16(lo);
    size_t o = (size_t)l * DD * 256 + (size_t)n * 256 + k;
    g_Bth[o] = *(unsigned short*)&hi;
    g_Btl[o] = *(unsigned short*)&lob;
}

// ---------------- aggregation: one warp per destination node ----------------
__global__ void agg_kernel(const float* __restrict__ x) {
    int gw   = (blockIdx.x * blockDim.x + threadIdx.x) >> 5;
    int lane = threadIdx.x & 31;
    if (gw >= NN) return;
    int beg = g_rowptr[gw], end = g_rowptr[gw + 1];
    float4 acc = make_float4(0.f, 0.f, 0.f, 0.f);
    const float* xb = x + lane * 4;
    for (int e = beg; e < end; e++) {
        int s = g_srcs[e];
        float4 v = *(const float4*)(xb + (size_t)s * DD);
        acc.x += v.x; acc.y += v.y; acc.z += v.z; acc.w += v.w;
    }
    *(float4*)(g_agg + (size_t)gw * DD + lane * 4) = acc;
}

// ---------------- tensor-core GEMM via mma.sync (HMMA) ------------------------
// out[m][n] = sum_k A[m][k] W[k][n] + bias[n];  A = [agg | x]  (virtual K=256).
// Split bf16: acc += Ahi*Bhi + Ahi*Blo + Alo*Bhi.
// BM=128, BN=128, BK=32, 256 threads = 8 warps, warp tile 64x32.
// smem rows padded to 40 bf16 (80B) -> conflict-free fragment loads.

#define BK 32
#define ROWB 80                       // padded row length (bytes)
#define BUFB 40960                    // 4 planes * 128 rows * 80B
#define OFF_AH 0
#define OFF_AL 10240
#define OFF_BH 20480
#define OFF_BL 30720

__device__ __forceinline__ void mma16816(float* c, const uint32_t* a, const uint32_t* b) {
    asm volatile(
        "mma.sync.aligned.m16n8k16.row.col.f32.bf16.bf16.f32 "
        "{%0,%1,%2,%3}, {%4,%5,%6,%7}, {%8,%9}, {%0,%1,%2,%3};"
        : "+f"(c[0]), "+f"(c[1]), "+f"(c[2]), "+f"(c[3])
        : "r"(a[0]), "r"(a[1]), "r"(a[2]), "r"(a[3]), "r"(b[0]), "r"(b[1]));
}

__device__ __forceinline__ uint32_t pack_bf2f(float a, float b) {
    __nv_bfloat16 ha = __float2bfloat16(a), hb = __float2bfloat16(b);
    uint16_t ua = *(uint16_t*)&ha, ub = *(uint16_t*)&hb;
    return (uint32_t)ua | ((uint32_t)ub << 16);
}

__global__ void __launch_bounds__(256) gemm_mma_kernel(
    const float* __restrict__ xin,
    int layer,
    const float* __restrict__ bias,
    float* __restrict__ out)
{
    extern __shared__ char smem[];
    int tid  = threadIdx.x;
    int wid  = tid >> 5;
    int lane = tid & 31;
    int g    = lane >> 2;
    int t    = lane & 3;
    int row0 = blockIdx.x * 128;
    int m0w  = (wid >> 2) * 64;
    int n0w  = (wid & 3) * 32;

    const uint32_t* Bth = (const uint32_t*)(g_Bth + (size_t)layer * DD * 256);
    const uint32_t* Btl = (const uint32_t*)(g_Btl + (size_t)layer * DD * 256);

    float acc[4][4][4];
    #pragma unroll
    for (int i = 0; i < 4; i++)
        #pragma unroll
        for (int j = 0; j < 4; j++)
            #pragma unroll
            for (int q = 0; q < 4; q++) acc[i][j][q] = 0.f;

    float4   av[4];
    uint32_t bhv[8], blv[8];

    auto load_regs = [&](int c) {
        int kv0 = c * BK;
        const float* src = (kv0 < DD) ? g_agg : xin;
        int kc = kv0 & 127;
        #pragma unroll
        for (int j = 0; j < 4; j++) {
            int p = j * 256 + tid;
            int m = p >> 3;
            int kq = p & 7;
            int grow = row0 + m;
            av[j] = make_float4(0.f, 0.f, 0.f, 0.f);
            if (grow < NN)
                av[j] = *(const float4*)(src + (size_t)grow * DD + kc + 4 * kq);
        }
        #pragma unroll
        for (int j = 0; j < 8; j++) {
            int p = j * 256 + tid;
            int n = p >> 4;
            int kp = p & 15;
            int ui = n * 128 + c * 16 + kp;
            bhv[j] = Bth[ui];
            blv[j] = Btl[ui];
        }
    };

    auto store_smem = [&](int buf) {
        char* base = smem + buf * BUFB;
        #pragma unroll
        for (int j = 0; j < 4; j++) {
            int p = j * 256 + tid;
            int m = p >> 3;
            int kq = p & 7;
            float4 v = av[j];
            float lx = v.x - __bfloat162float(__float2bfloat16(v.x));
            float ly = v.y - __bfloat162float(__float2bfloat16(v.y));
            float lz = v.z - __bfloat162float(__float2bfloat16(v.z));
            float lw = v.w - __bfloat162float(__float2bfloat16(v.w));
            uint32_t off = (uint32_t)m * ROWB + 8 * kq;
            *(uint32_t*)(base + OFF_AH + off)     = pack_bf2f(v.x, v.y);
            *(uint32_t*)(base + OFF_AH + off + 4) = pack_bf2f(v.z, v.w);
            *(uint32_t*)(base + OFF_AL + off)     = pack_bf2f(lx, ly);
            *(uint32_t*)(base + OFF_AL + off + 4) = pack_bf2f(lz, lw);
        }
        #pragma unroll
        for (int j = 0; j < 8; j++) {
            int p = j * 256 + tid;
            int n = p >> 4;
            int kp = p & 15;
            uint32_t off = (uint32_t)n * ROWB + 4 * kp;
            *(uint32_t*)(base + OFF_BH + off) = bhv[j];
            *(uint32_t*)(base + OFF_BL + off) = blv[j];
        }
    };

    load_regs(0);
    store_smem(0);
    __syncthreads();

    #pragma unroll 1
    for (int c = 0; c < 8; c++) {
        if (c < 7) load_regs(c + 1);

        const char* base = smem + (c & 1) * BUFB;
        #pragma unroll
        for (int s = 0; s < 2; s++) {
            uint32_t ah[4][4], al[4][4], bh[4][2], bl[4][2];
            #pragma unroll
            for (int mt = 0; mt < 4; mt++) {
                uint32_t r0 = (uint32_t)(m0w + mt * 16 + g) * ROWB + s * 32 + 4 * t;
                uint32_t r1 = r0 + 8 * ROWB;
                ah[mt][0] = *(const uint32_t*)(base + OFF_AH + r0);
                ah[mt][1] = *(const uint32_t*)(base + OFF_AH + r1);
                ah[mt][2] = *(const uint32_t*)(base + OFF_AH + r0 + 16);
                ah[mt][3] = *(const uint32_t*)(base + OFF_AH + r1 + 16);
                al[mt][0] = *(const uint32_t*)(base + OFF_AL + r0);
                al[mt][1] = *(const uint32_t*)(base + OFF_AL + r1);
                al[mt][2] = *(const uint32_t*)(base + OFF_AL + r0 + 16);
                al[mt][3] = *(const uint32_t*)(base + OFF_AL + r1 + 16);
            }
            #pragma unroll
            for (int nt = 0; nt < 4; nt++) {
                uint32_t rb = (uint32_t)(n0w + nt * 8 + g) * ROWB + s * 32 + 4 * t;
                bh[nt][0] = *(const uint32_t*)(base + OFF_BH + rb);
                bh[nt][1] = *(const uint32_t*)(base + OFF_BH + rb + 16);
                bl[nt][0] = *(const uint32_t*)(base + OFF_BL + rb);
                bl[nt][1] = *(const uint32_t*)(base + OFF_BL + rb + 16);
            }
            #pragma unroll
            for (int mt = 0; mt < 4; mt++)
                #pragma unroll
                for (int nt = 0; nt < 4; nt++) {
                    mma16816(acc[mt][nt], ah[mt], bh[nt]);
                    mma16816(acc[mt][nt], ah[mt], bl[nt]);
                    mma16816(acc[mt][nt], al[mt], bh[nt]);
                }
        }
        // store writes the OTHER buffer; one sync per iteration suffices
        if (c < 7) {
            store_smem((c + 1) & 1);
            __syncthreads();
        }
    }

    #pragma unroll
    for (int nt = 0; nt < 4; nt++) {
        int col = n0w + nt * 8 + 2 * t;
        float b0 = bias[col], b1 = bias[col + 1];
        #pragma unroll
        for (int mt = 0; mt < 4; mt++) {
            int r = row0 + m0w + mt * 16 + g;
            if (r < NN) {
                float2 o0 = make_float2(acc[mt][nt][0] + b0, acc[mt][nt][1] + b1);
                *(float2*)(out + (size_t)r * DD + col) = o0;
            }
            if (r + 8 < NN) {
                float2 o1 = make_float2(acc[mt][nt][2] + b0, acc[mt][nt][3] + b1);
                *(float2*)(out + (size_t)(r + 8) * DD + col) = o1;
            }
        }
    }
}

// ---------------- launch ----------------
extern "C" void kernel_launch(void* const* d_in, const int* in_sizes, int n_in,
                              void* d_out, int out_size) {
    const float* x     = (const float*)d_in[0];
    const void*  edges = d_in[1];
    const float* Wrel  = (const float*)d_in[2];
    const float* Wroot = (const float*)d_in[3];
    const float* bias  = (const float*)d_in[4];
    float*       out   = (float*)d_out;

    float *buf0, *buf1;
    cudaGetSymbolAddress((void**)&buf0, g_buf0);
    cudaGetSymbolAddress((void**)&buf1, g_buf1);

    cudaFuncSetAttribute(gemm_mma_kernel,
                         cudaFuncAttributeMaxDynamicSharedMemorySize, 2 * BUFB);

    const int T = 256;
    int gbN = (NN + T - 1) / T;
    int gbE = (EE + T - 1) / T;

    zero_counts_kernel<<<gbN, T>>>();
    detect_kernel<<<16, 256>>>((const unsigned int*)edges);
    convert_hist_kernel<<<gbE, T>>>(edges);
    scan_red_kernel<<<NB, 256>>>();
    scan_mid_kernel<<<1, 256>>>();
    scan_final_kernel<<<NB, 256>>>();
    fill_kernel<<<gbE, T>>>();
    wprep_kernel<<<(LL * 256 * DD + T - 1) / T, T>>>(Wrel, Wroot);

    int aggBlocks  = (NN * 32 + T - 1) / T;
    int gemmBlocks = (NN + 127) / 128;   // 391

    const float* cur = x;
    float* outs[LL] = { buf0, buf1, out };
    for (int l = 0; l < LL; l++) {
        agg_kernel<<<aggBlocks, T>>>(cur);
        gemm_mma_kernel<<<gemmBlocks, T, 2 * BUFB>>>(cur, l, bias + (size_t)l * DD,
                                                     outs[l]);
        cur = outs[l];
    }
}